// round 1
// baseline (speedup 1.0000x reference)
#include <cuda_runtime.h>
#include <math.h>

#define MB   256    // batch
#define TX   256    // encoder time
#define FDIM 128    // input features
#define NA   256    // encoder hidden per direction
#define NS   512    // decoder hidden (= 2*NA)
#define VOC  1024
#define AH   10     // attention hidden
#define TYD  10     // decoder steps

// ---------------- scratch (device globals; no allocations) ----------------
__device__ float g_gin[2][TX][MB][4 * NA];   // input-projected gates, per dir / proc-step
__device__ float g_a[TX][MB][NS];            // encoder hidden states [t][m][fwd|bwd]
__device__ float g_c[2][MB][NA];             // encoder cell state (per-thread owned)
__device__ float g_Ea[MB][TX][AH];           // hoisted a @ W1a^T
__device__ float g_ctx[MB][NS];              // attention context
__device__ float g_sbuf[2][MB][NS];          // decoder hidden (ping-pong)
__device__ float g_cdec[MB][NS];             // decoder cell state

__device__ __forceinline__ float sigf(float x) { return 1.f / (1.f + expf(-x)); }

// ---------------- encoder input projection: Gin = X @ Wih^T + b ----------------
// rows r = t*256 + m (65536 per dir), cols = 1024 gates, K = 128.
// 64x64 tile, 256 threads, 4x4 microtile.
__global__ void xproj_kernel(const float* __restrict__ X,
                             const float* __restrict__ Wf, const float* __restrict__ bf,
                             const float* __restrict__ Wb, const float* __restrict__ bb)
{
    int d = blockIdx.z;
    const float* W    = d ? Wb : Wf;
    const float* bias = d ? bb : bf;
    int col0 = blockIdx.x * 64;
    int row0 = blockIdx.y * 64;
    int t  = row0 >> 8;          // 64 | 256, so t constant within tile
    int m0 = row0 & 255;
    int xt = d ? (TX - 1 - t) : t;

    __shared__ float As[16][64];
    __shared__ float Bs[16][64];
    int tid = threadIdx.x;
    int ry = tid >> 4, rx = tid & 15;
    float acc[4][4] = {};

    int lr = tid >> 2;           // 0..63
    int lk = (tid & 3) * 4;      // 0,4,8,12

    const float* Ab = X + ((size_t)m0 * TX + xt) * FDIM;
    for (int k0 = 0; k0 < FDIM; k0 += 16) {
        float4 av = *(const float4*)(Ab + (size_t)lr * TX * FDIM + k0 + lk);
        float4 bv = *(const float4*)(W + (size_t)(col0 + lr) * FDIM + k0 + lk);
        As[lk + 0][lr] = av.x; As[lk + 1][lr] = av.y; As[lk + 2][lr] = av.z; As[lk + 3][lr] = av.w;
        Bs[lk + 0][lr] = bv.x; Bs[lk + 1][lr] = bv.y; Bs[lk + 2][lr] = bv.z; Bs[lk + 3][lr] = bv.w;
        __syncthreads();
        #pragma unroll
        for (int kk = 0; kk < 16; kk++) {
            float a_[4], b_[4];
            #pragma unroll
            for (int i = 0; i < 4; i++) a_[i] = As[kk][ry + 16 * i];
            #pragma unroll
            for (int j = 0; j < 4; j++) b_[j] = Bs[kk][rx + 16 * j];
            #pragma unroll
            for (int i = 0; i < 4; i++)
                #pragma unroll
                for (int j = 0; j < 4; j++)
                    acc[i][j] += a_[i] * b_[j];
        }
        __syncthreads();
    }
    #pragma unroll
    for (int i = 0; i < 4; i++) {
        int m = m0 + ry + 16 * i;
        float* outp = &g_gin[d][t][m][0];
        #pragma unroll
        for (int j = 0; j < 4; j++) {
            int c = col0 + rx + 16 * j;
            outp[c] = acc[i][j] + bias[c];
        }
    }
}

// ---------------- one recurrence timestep, both directions ----------------
// block: 16 units x 64 m. thread (ul, mg): 4 m-rows x 4 gates. K = 256.
__global__ void lstm_step_kernel(const float* __restrict__ Whf,
                                 const float* __restrict__ Whb, int t)
{
    int d = blockIdx.z;
    const float* W = d ? Whb : Whf;
    int u0 = blockIdx.x * 16;
    int m0 = blockIdx.y * 64;
    int tid = threadIdx.x;
    int ul = tid & 15;
    int mg = tid >> 4;           // 0..15
    int u = u0 + ul;

    __shared__ float As[64][33];
    __shared__ float Ws[64][33]; // [g*16+uu][k]

    float acc[4][4];
    {
        const float* gin = &g_gin[d][t][0][0];
        #pragma unroll
        for (int mi = 0; mi < 4; mi++) {
            int m = m0 + mg * 4 + mi;
            #pragma unroll
            for (int g = 0; g < 4; g++)
                acc[mi][g] = gin[(size_t)m * (4 * NA) + g * NA + u];
        }
    }

    int tp = (t == 0) ? 0 : (d == 0 ? t - 1 : TX - t);
    const float* aprev = &g_a[tp][0][d * NA];

    for (int k0 = 0; k0 < NA; k0 += 32) {
        #pragma unroll
        for (int i = 0; i < 8; i++) {
            int lin = tid + 256 * i;
            int row = lin >> 5, k = lin & 31;
            As[row][k] = (t == 0) ? 0.f : aprev[(size_t)(m0 + row) * NS + k0 + k];
        }
        #pragma unroll
        for (int i = 0; i < 8; i++) {
            int lin = tid + 256 * i;
            int gr = lin >> 5, k = lin & 31;
            int g = gr >> 4, uu = gr & 15;
            Ws[gr][k] = W[(size_t)(g * NA + u0 + uu) * NA + k0 + k];
        }
        __syncthreads();
        #pragma unroll
        for (int kk = 0; kk < 32; kk++) {
            float a_[4], w_[4];
            #pragma unroll
            for (int mi = 0; mi < 4; mi++) a_[mi] = As[mg * 4 + mi][kk];
            #pragma unroll
            for (int g = 0; g < 4; g++) w_[g] = Ws[g * 16 + ul][kk];
            #pragma unroll
            for (int mi = 0; mi < 4; mi++)
                #pragma unroll
                for (int g = 0; g < 4; g++)
                    acc[mi][g] += a_[mi] * w_[g];
        }
        __syncthreads();
    }

    int tw = d ? (TX - 1 - t) : t;
    #pragma unroll
    for (int mi = 0; mi < 4; mi++) {
        int m = m0 + mg * 4 + mi;
        float ig = sigf(acc[mi][0]);
        float fg = sigf(acc[mi][1]);
        float gg = tanhf(acc[mi][2]);
        float og = sigf(acc[mi][3]);
        float co = (t == 0) ? 0.f : g_c[d][m][u];
        float cn = fg * co + ig * gg;
        g_c[d][m][u] = cn;
        g_a[tw][m][d * NA + u] = og * tanhf(cn);
    }
}

// ---------------- hoisted attention energies: Ea = a @ W1a^T ----------------
// one thread per (t,m) row; W1a transposed in shared; broadcast LDS.
__global__ void ea_kernel(const float* __restrict__ W1)
{
    __shared__ float W1t[512][AH];
    int tid = threadIdx.x;
    for (int i = tid; i < 512 * AH; i += 256) {
        int h = i / 512, k = i - h * 512;
        W1t[k][h] = W1[h * 1024 + k];
    }
    __syncthreads();
    int r = blockIdx.x * 256 + tid;                  // r = t*MB + m
    const float* arow = &g_a[0][0][0] + (size_t)r * NS;
    float e[AH] = {};
    for (int k = 0; k < 512; k += 4) {
        float4 av = *(const float4*)(arow + k);
        #pragma unroll
        for (int h = 0; h < AH; h++)
            e[h] += av.x * W1t[k][h] + av.y * W1t[k + 1][h]
                  + av.z * W1t[k + 2][h] + av.w * W1t[k + 3][h];
    }
    int tt = r >> 8;
    int m = r & 255;
    float* eo = &g_Ea[m][tt][0];
    #pragma unroll
    for (int h = 0; h < AH; h++) eo[h] = e[h];
}

__global__ void init_dec_kernel()
{
    int i = blockIdx.x * 256 + threadIdx.x;
    if (i < MB * NS) {
        (&g_sbuf[0][0][0])[i] = 0.f;
        (&g_cdec[0][0])[i] = 0.f;
    }
}

// ---------------- attention: Es + scores + softmax + context, per m ----------------
__global__ void attention_kernel(const float* __restrict__ W1, const float* __restrict__ b1,
                                 const float* __restrict__ W2, const float* __restrict__ b2,
                                 int pin)
{
    int m = blockIdx.x;
    int tid = threadIdx.x;
    int lane = tid & 31, warp = tid >> 5;
    __shared__ float Ss[NS];
    __shared__ float EsSh[AH];
    __shared__ float alpha[TX];
    __shared__ float red[8];
    __shared__ float sh_mx, sh_sum;

    const float* s_in = &g_sbuf[pin][m][0];
    Ss[tid] = s_in[tid];
    Ss[tid + 256] = s_in[tid + 256];
    __syncthreads();

    for (int h = warp; h < AH; h += 8) {
        float p = 0.f;
        for (int k = lane; k < NS; k += 32)
            p += Ss[k] * W1[h * 1024 + 512 + k];
        #pragma unroll
        for (int o = 16; o; o >>= 1) p += __shfl_xor_sync(0xffffffffu, p, o);
        if (lane == 0) EsSh[h] = p + b1[h];
    }
    __syncthreads();

    float sc = b2[0];
    {
        const float* ea = &g_Ea[m][tid][0];
        #pragma unroll
        for (int h = 0; h < AH; h++)
            sc += W2[h] * tanhf(ea[h] + EsSh[h]);
    }
    sc = fmaxf(sc, 0.f);

    float v = sc;
    #pragma unroll
    for (int o = 16; o; o >>= 1) v = fmaxf(v, __shfl_xor_sync(0xffffffffu, v, o));
    if (lane == 0) red[warp] = v;
    __syncthreads();
    if (tid == 0) {
        float mx = red[0];
        #pragma unroll
        for (int i = 1; i < 8; i++) mx = fmaxf(mx, red[i]);
        sh_mx = mx;
    }
    __syncthreads();
    float ev = expf(sc - sh_mx);
    float sv = ev;
    #pragma unroll
    for (int o = 16; o; o >>= 1) sv += __shfl_xor_sync(0xffffffffu, sv, o);
    if (lane == 0) red[warp] = sv;
    __syncthreads();
    if (tid == 0) {
        float s = 0.f;
        #pragma unroll
        for (int i = 0; i < 8; i++) s += red[i];
        sh_sum = s;
    }
    __syncthreads();
    alpha[tid] = ev / sh_sum;
    __syncthreads();

    const float* abase = &g_a[0][m][0];
    for (int j = tid; j < NS; j += 256) {
        float accv = 0.f;
        #pragma unroll 8
        for (int t2 = 0; t2 < TX; t2++)
            accv += alpha[t2] * abase[(size_t)t2 * MB * NS + j];
        g_ctx[m][j] = accv;
    }
}

// ---------------- decoder LSTM cell (fused GEMM over [ctx; s] + gates) ----------------
__global__ void dec_cell_kernel(const float* __restrict__ Wih, const float* __restrict__ Whh,
                                const float* __restrict__ bc, int pin)
{
    int u0 = blockIdx.x * 16;    // grid.x = 32 -> 512 units
    int m0 = blockIdx.y * 64;    // grid.y = 4
    int tid = threadIdx.x;
    int ul = tid & 15, mg = tid >> 4;
    int u = u0 + ul;

    __shared__ float As[64][33];
    __shared__ float Ws[64][33];

    float acc[4][4];
    #pragma unroll
    for (int mi = 0; mi < 4; mi++)
        #pragma unroll
        for (int g = 0; g < 4; g++)
            acc[mi][g] = bc[g * NS + u];

    for (int ph = 0; ph < 2; ph++) {
        const float* Arow = ph ? &g_sbuf[pin][0][0] : &g_ctx[0][0];
        const float* W = ph ? Whh : Wih;
        for (int k0 = 0; k0 < NS; k0 += 32) {
            #pragma unroll
            for (int i = 0; i < 8; i++) {
                int lin = tid + 256 * i;
                int row = lin >> 5, k = lin & 31;
                As[row][k] = Arow[(size_t)(m0 + row) * NS + k0 + k];
            }
            #pragma unroll
            for (int i = 0; i < 8; i++) {
                int lin = tid + 256 * i;
                int gr = lin >> 5, k = lin & 31;
                int g = gr >> 4, uu = gr & 15;
                Ws[gr][k] = W[(size_t)(g * NS + u0 + uu) * NS + k0 + k];
            }
            __syncthreads();
            #pragma unroll
            for (int kk = 0; kk < 32; kk++) {
                float a_[4], w_[4];
                #pragma unroll
                for (int mi = 0; mi < 4; mi++) a_[mi] = As[mg * 4 + mi][kk];
                #pragma unroll
                for (int g = 0; g < 4; g++) w_[g] = Ws[g * 16 + ul][kk];
                #pragma unroll
                for (int mi = 0; mi < 4; mi++)
                    #pragma unroll
                    for (int g = 0; g < 4; g++)
                        acc[mi][g] += a_[mi] * w_[g];
            }
            __syncthreads();
        }
    }

    #pragma unroll
    for (int mi = 0; mi < 4; mi++) {
        int m = m0 + mg * 4 + mi;
        float ig = sigf(acc[mi][0]);
        float fg = sigf(acc[mi][1]);
        float gg = tanhf(acc[mi][2]);
        float og = sigf(acc[mi][3]);
        float co = g_cdec[m][u];
        float cn = fg * co + ig * gg;
        g_cdec[m][u] = cn;
        g_sbuf[1 - pin][m][u] = og * tanhf(cn);
    }
}

// ---------------- output projection: out[:, ty, :] = s_new @ Wfc^T + bfc ----------------
__global__ void fc_kernel(const float* __restrict__ Wfc, const float* __restrict__ bfc,
                          float* __restrict__ outp, int ps, int ty)
{
    int col0 = blockIdx.x * 64;
    int m0 = blockIdx.y * 64;
    int tid = threadIdx.x;
    int ry = tid >> 4, rx = tid & 15;
    __shared__ float As[16][64];
    __shared__ float Bs[16][64];
    float acc[4][4] = {};
    int lr = tid >> 2;
    int lk = (tid & 3) * 4;
    const float* S = &g_sbuf[ps][0][0];
    for (int k0 = 0; k0 < NS; k0 += 16) {
        float4 av = *(const float4*)(S + (size_t)(m0 + lr) * NS + k0 + lk);
        float4 bv = *(const float4*)(Wfc + (size_t)(col0 + lr) * NS + k0 + lk);
        As[lk + 0][lr] = av.x; As[lk + 1][lr] = av.y; As[lk + 2][lr] = av.z; As[lk + 3][lr] = av.w;
        Bs[lk + 0][lr] = bv.x; Bs[lk + 1][lr] = bv.y; Bs[lk + 2][lr] = bv.z; Bs[lk + 3][lr] = bv.w;
        __syncthreads();
        #pragma unroll
        for (int kk = 0; kk < 16; kk++) {
            float a_[4], b_[4];
            #pragma unroll
            for (int i = 0; i < 4; i++) a_[i] = As[kk][ry + 16 * i];
            #pragma unroll
            for (int j = 0; j < 4; j++) b_[j] = Bs[kk][rx + 16 * j];
            #pragma unroll
            for (int i = 0; i < 4; i++)
                #pragma unroll
                for (int j = 0; j < 4; j++)
                    acc[i][j] += a_[i] * b_[j];
        }
        __syncthreads();
    }
    #pragma unroll
    for (int i = 0; i < 4; i++) {
        int m = m0 + ry + 16 * i;
        #pragma unroll
        for (int j = 0; j < 4; j++) {
            int c = col0 + rx + 16 * j;
            outp[((size_t)m * TYD + ty) * VOC + c] = acc[i][j] + bfc[c];
        }
    }
}

// ---------------- launch ----------------
extern "C" void kernel_launch(void* const* d_in, const int* in_sizes, int n_in,
                              void* d_out, int out_size)
{
    const float* X     = (const float*)d_in[0];
    const float* Wih_f = (const float*)d_in[1];
    const float* Whh_f = (const float*)d_in[2];
    const float* b_f   = (const float*)d_in[3];
    const float* Wih_b = (const float*)d_in[4];
    const float* Whh_b = (const float*)d_in[5];
    const float* b_b   = (const float*)d_in[6];
    const float* W1    = (const float*)d_in[7];
    const float* b1    = (const float*)d_in[8];
    const float* W2    = (const float*)d_in[9];
    const float* b2    = (const float*)d_in[10];
    const float* Wc_ih = (const float*)d_in[11];
    const float* Wc_hh = (const float*)d_in[12];
    const float* bc    = (const float*)d_in[13];
    const float* Wfc   = (const float*)d_in[14];
    const float* bfc   = (const float*)d_in[15];
    float* outp = (float*)d_out;

    // encoder input projection (both directions)
    xproj_kernel<<<dim3(16, 1024, 2), 256>>>(X, Wih_f, b_f, Wih_b, b_b);

    // sequential recurrence
    for (int t = 0; t < TX; t++)
        lstm_step_kernel<<<dim3(16, 4, 2), 256>>>(Whh_f, Whh_b, t);

    // hoisted attention energies + decoder state init
    ea_kernel<<<256, 256>>>(W1);
    init_dec_kernel<<<512, 256>>>();

    int pin = 0;
    for (int ty = 0; ty < TYD; ty++) {
        attention_kernel<<<MB, 256>>>(W1, b1, W2, b2, pin);
        dec_cell_kernel<<<dim3(32, 4), 256>>>(Wc_ih, Wc_hh, bc, pin);
        fc_kernel<<<dim3(16, 4), 256>>>(Wfc, bfc, outp, 1 - pin, ty);
        pin = 1 - pin;
    }
}

// round 2
// speedup vs baseline: 1.5066x; 1.5066x over previous
#include <cuda_runtime.h>
#include <math.h>

#define MB   256    // batch
#define TX   256    // encoder time
#define FDIM 128    // input features
#define NA   256    // encoder hidden per direction
#define NS   512    // decoder hidden (= 2*NA)
#define VOC  1024
#define AH   10     // attention hidden
#define TYD  10     // decoder steps

// ---------------- scratch (device globals; no allocations) ----------------
__device__ float g_gin[2][TX][MB][4 * NA];   // input-projected gates
__device__ float g_a[TX][MB][NS];            // encoder hidden states [t][m][fwd|bwd]
__device__ float g_hT[2][NA][MB];            // transposed latest h, per dir: [d][u][m]
__device__ float g_Ea[MB][TX][AH];           // hoisted a @ W1a^T
__device__ float g_ctx[MB][NS];              // attention context
__device__ float g_sbuf[2][MB][NS];          // decoder hidden (ping-pong)
__device__ float g_cdec[MB][NS];             // decoder cell state
__device__ unsigned g_bar[8];                // per-(dir, m-tile) barrier counters

__device__ __forceinline__ float sigf(float x) { return 1.f / (1.f + expf(-x)); }
// fast versions for the recurrence epilogue
__device__ __forceinline__ float fsig(float x) { return __fdividef(1.f, 1.f + __expf(-x)); }
__device__ __forceinline__ float ftanh(float x) { return 1.f - __fdividef(2.f, __expf(2.f * x) + 1.f); }

#define FMA2(acc, a, b) asm("fma.rn.f32x2 %0, %1, %2, %0;" : "+l"(acc) : "l"(a), "l"(b))
#define PACK2(d, lo, hi) asm("mov.b64 %0, {%1, %2};" : "=l"(d) : "f"(lo), "f"(hi))
#define UNPACK2(lo, hi, v) asm("mov.b64 {%0, %1}, %2;" : "=f"(lo), "=f"(hi) : "l"(v))

// ---------------- encoder input projection: Gin = X @ Wih^T + b ----------------
__global__ void xproj_kernel(const float* __restrict__ X,
                             const float* __restrict__ Wf, const float* __restrict__ bf,
                             const float* __restrict__ Wb, const float* __restrict__ bb)
{
    int d = blockIdx.z;
    const float* W    = d ? Wb : Wf;
    const float* bias = d ? bb : bf;
    int col0 = blockIdx.x * 64;
    int row0 = blockIdx.y * 64;
    int t  = row0 >> 8;
    int m0 = row0 & 255;
    int xt = d ? (TX - 1 - t) : t;

    __shared__ float As[16][64];
    __shared__ float Bs[16][64];
    int tid = threadIdx.x;
    int ry = tid >> 4, rx = tid & 15;
    float acc[4][4] = {};

    int lr = tid >> 2;
    int lk = (tid & 3) * 4;

    const float* Ab = X + ((size_t)m0 * TX + xt) * FDIM;
    for (int k0 = 0; k0 < FDIM; k0 += 16) {
        float4 av = *(const float4*)(Ab + (size_t)lr * TX * FDIM + k0 + lk);
        float4 bv = *(const float4*)(W + (size_t)(col0 + lr) * FDIM + k0 + lk);
        As[lk + 0][lr] = av.x; As[lk + 1][lr] = av.y; As[lk + 2][lr] = av.z; As[lk + 3][lr] = av.w;
        Bs[lk + 0][lr] = bv.x; Bs[lk + 1][lr] = bv.y; Bs[lk + 2][lr] = bv.z; Bs[lk + 3][lr] = bv.w;
        __syncthreads();
        #pragma unroll
        for (int kk = 0; kk < 16; kk++) {
            float a_[4], b_[4];
            #pragma unroll
            for (int i = 0; i < 4; i++) a_[i] = As[kk][ry + 16 * i];
            #pragma unroll
            for (int j = 0; j < 4; j++) b_[j] = Bs[kk][rx + 16 * j];
            #pragma unroll
            for (int i = 0; i < 4; i++)
                #pragma unroll
                for (int j = 0; j < 4; j++)
                    acc[i][j] += a_[i] * b_[j];
        }
        __syncthreads();
    }
    #pragma unroll
    for (int i = 0; i < 4; i++) {
        int m = m0 + ry + 16 * i;
        float* outp = &g_gin[d][t][m][0];
        #pragma unroll
        for (int j = 0; j < 4; j++) {
            int c = col0 + rx + 16 * j;
            outp[c] = acc[i][j] + bias[c];
        }
    }
}

__global__ void zero_bar_kernel()
{
    if (threadIdx.x < 8) g_bar[threadIdx.x] = 0u;
}

// ---------------- persistent recurrence: all 256 steps, both directions ----------------
// grid (16 u-tiles, 4 m-tiles, 2 dirs) = 128 blocks, 128 threads, 192KB smem.
// thread (ul 0..15, mg 0..7): unit u0+ul, m rows m0+mg*8 .. +7, all 4 gates.
// Ws: [k 256][128] gate weights DUPLICATED ({w,w} pairs) -> ld.shared.v2.u64 gives f32x2-ready operands.
// As: [k 256][64]  h_prev transposed.
__global__ void __launch_bounds__(128, 1) lstm_all_kernel(const float* __restrict__ Whf,
                                                          const float* __restrict__ Whb)
{
    extern __shared__ float sm[];
    float* Ws = sm;                 // 256*128 floats = 128KB
    float* As = sm + 256 * 128;     // 256*64  floats = 64KB

    int d = blockIdx.z;
    const float* W = d ? Whb : Whf;
    int u0 = blockIdx.x * 16;
    int m0 = blockIdx.y * 64;
    int tid = threadIdx.x;
    int ul = tid & 15, mg = tid >> 4;
    int u = u0 + ul;
    unsigned* barp = &g_bar[d * 4 + blockIdx.y];

    // one-time Ws fill (duplicated pairs)
    for (int idx = tid; idx < 64 * 64; idx += 128) {
        int r  = idx >> 6;           // 0..63 == uu*4+g
        int k4 = idx & 63;
        int uu = r >> 2, g = r & 3;
        float4 w4 = *(const float4*)&W[(size_t)(g * NA + u0 + uu) * NA + k4 * 4];
        float vv[4] = {w4.x, w4.y, w4.z, w4.w};
        #pragma unroll
        for (int j = 0; j < 4; j++) {
            int k = k4 * 4 + j;
            Ws[k * 128 + r * 2 + 0] = vv[j];
            Ws[k * 128 + r * 2 + 1] = vv[j];
        }
    }

    float c[8];
    #pragma unroll
    for (int i = 0; i < 8; i++) c[i] = 0.f;

    // prefetch gin for t=0
    float rg[8][4];
    {
        const float* gb = &g_gin[d][0][0][0];
        #pragma unroll
        for (int mi = 0; mi < 8; mi++) {
            int m = m0 + mg * 8 + mi;
            #pragma unroll
            for (int g = 0; g < 4; g++)
                rg[mi][g] = gb[(size_t)m * 1024 + g * 256 + u];
        }
    }

    for (int t = 0; t < TX; t++) {
        // ---- As fill ----
        if (t == 0) {
            float4 z = make_float4(0.f, 0.f, 0.f, 0.f);
            for (int idx = tid; idx < 4096; idx += 128)
                ((float4*)As)[idx] = z;
        } else {
            for (int idx = tid; idx < 4096; idx += 128) {
                int m4 = idx & 15;
                int k  = idx >> 4;
                float4 v = __ldcg((const float4*)&g_hT[d][k][m0 + m4 * 4]);
                *(float4*)&As[k * 64 + m4 * 4] = v;
            }
        }
        __syncthreads();

        // ---- init accumulators from gin ----
        unsigned long long acc2[4][4];
        #pragma unroll
        for (int p = 0; p < 4; p++)
            #pragma unroll
            for (int g = 0; g < 4; g++)
                PACK2(acc2[p][g], rg[2 * p][g], rg[2 * p + 1][g]);

        // ---- K loop ----
        #pragma unroll 4
        for (int k = 0; k < NA; k++) {
            ulonglong2 aL = *(const ulonglong2*)&As[k * 64 + mg * 8];
            ulonglong2 aH = *(const ulonglong2*)&As[k * 64 + mg * 8 + 4];
            ulonglong2 wA = *(const ulonglong2*)&Ws[k * 128 + ul * 8];
            ulonglong2 wB = *(const ulonglong2*)&Ws[k * 128 + ul * 8 + 4];
            FMA2(acc2[0][0], aL.x, wA.x); FMA2(acc2[0][1], aL.x, wA.y);
            FMA2(acc2[0][2], aL.x, wB.x); FMA2(acc2[0][3], aL.x, wB.y);
            FMA2(acc2[1][0], aL.y, wA.x); FMA2(acc2[1][1], aL.y, wA.y);
            FMA2(acc2[1][2], aL.y, wB.x); FMA2(acc2[1][3], aL.y, wB.y);
            FMA2(acc2[2][0], aH.x, wA.x); FMA2(acc2[2][1], aH.x, wA.y);
            FMA2(acc2[2][2], aH.x, wB.x); FMA2(acc2[2][3], aH.x, wB.y);
            FMA2(acc2[3][0], aH.y, wA.x); FMA2(acc2[3][1], aH.y, wA.y);
            FMA2(acc2[3][2], aH.y, wB.x); FMA2(acc2[3][3], aH.y, wB.y);
        }

        // ---- gates, state update, h writes ----
        int tw = d ? (TX - 1 - t) : t;
        #pragma unroll
        for (int p = 0; p < 4; p++) {
            float i0, i1, f0, f1, g0, g1, o0, o1;
            UNPACK2(i0, i1, acc2[p][0]);
            UNPACK2(f0, f1, acc2[p][1]);
            UNPACK2(g0, g1, acc2[p][2]);
            UNPACK2(o0, o1, acc2[p][3]);
            {
                int e = 2 * p;
                float cn = fsig(f0) * c[e] + fsig(i0) * ftanh(g0);
                c[e] = cn;
                float h = fsig(o0) * ftanh(cn);
                int m = m0 + mg * 8 + e;
                __stcg(&g_hT[d][u][m], h);
                g_a[tw][m][d * NA + u] = h;
            }
            {
                int e = 2 * p + 1;
                float cn = fsig(f1) * c[e] + fsig(i1) * ftanh(g1);
                c[e] = cn;
                float h = fsig(o1) * ftanh(cn);
                int m = m0 + mg * 8 + e;
                __stcg(&g_hT[d][u][m], h);
                g_a[tw][m][d * NA + u] = h;
            }
        }

        // ---- prefetch gin for t+1 (overlaps barrier) ----
        if (t + 1 < TX) {
            const float* gb = &g_gin[d][t + 1][0][0];
            #pragma unroll
            for (int mi = 0; mi < 8; mi++) {
                int m = m0 + mg * 8 + mi;
                #pragma unroll
                for (int g = 0; g < 4; g++)
                    rg[mi][g] = gb[(size_t)m * 1024 + g * 256 + u];
            }
        }

        // ---- inter-block barrier (group = 16 blocks sharing (dir, m-tile)) ----
        if (t + 1 < TX) {
            __threadfence();
            __syncthreads();
            if (tid == 0) {
                atomicAdd(barp, 1u);
                unsigned tgt = 16u * (unsigned)(t + 1);
                while (atomicAdd(barp, 0u) < tgt) {}
            }
            __syncthreads();
        }
    }
}

// ---------------- hoisted attention energies: Ea = a @ W1a^T ----------------
__global__ void ea_kernel(const float* __restrict__ W1)
{
    __shared__ float W1t[512][AH];
    int tid = threadIdx.x;
    for (int i = tid; i < 512 * AH; i += 256) {
        int h = i / 512, k = i - h * 512;
        W1t[k][h] = W1[h * 1024 + k];
    }
    __syncthreads();
    int r = blockIdx.x * 256 + tid;
    const float* arow = &g_a[0][0][0] + (size_t)r * NS;
    float e[AH] = {};
    for (int k = 0; k < 512; k += 4) {
        float4 av = *(const float4*)(arow + k);
        #pragma unroll
        for (int h = 0; h < AH; h++)
            e[h] += av.x * W1t[k][h] + av.y * W1t[k + 1][h]
                  + av.z * W1t[k + 2][h] + av.w * W1t[k + 3][h];
    }
    int tt = r >> 8;
    int m = r & 255;
    float* eo = &g_Ea[m][tt][0];
    #pragma unroll
    for (int h = 0; h < AH; h++) eo[h] = e[h];
}

__global__ void init_dec_kernel()
{
    int i = blockIdx.x * 256 + threadIdx.x;
    if (i < MB * NS) {
        (&g_sbuf[0][0][0])[i] = 0.f;
        (&g_cdec[0][0])[i] = 0.f;
    }
}

// ---------------- attention: Es + scores + softmax + context, per m ----------------
__global__ void attention_kernel(const float* __restrict__ W1, const float* __restrict__ b1,
                                 const float* __restrict__ W2, const float* __restrict__ b2,
                                 int pin)
{
    int m = blockIdx.x;
    int tid = threadIdx.x;
    int lane = tid & 31, warp = tid >> 5;
    __shared__ float Ss[NS];
    __shared__ float EsSh[AH];
    __shared__ float alpha[TX];
    __shared__ float red[8];
    __shared__ float sh_mx, sh_sum;

    const float* s_in = &g_sbuf[pin][m][0];
    Ss[tid] = s_in[tid];
    Ss[tid + 256] = s_in[tid + 256];
    __syncthreads();

    for (int h = warp; h < AH; h += 8) {
        float p = 0.f;
        for (int k = lane; k < NS; k += 32)
            p += Ss[k] * W1[h * 1024 + 512 + k];
        #pragma unroll
        for (int o = 16; o; o >>= 1) p += __shfl_xor_sync(0xffffffffu, p, o);
        if (lane == 0) EsSh[h] = p + b1[h];
    }
    __syncthreads();

    float sc = b2[0];
    {
        const float* ea = &g_Ea[m][tid][0];
        #pragma unroll
        for (int h = 0; h < AH; h++)
            sc += W2[h] * tanhf(ea[h] + EsSh[h]);
    }
    sc = fmaxf(sc, 0.f);

    float v = sc;
    #pragma unroll
    for (int o = 16; o; o >>= 1) v = fmaxf(v, __shfl_xor_sync(0xffffffffu, v, o));
    if (lane == 0) red[warp] = v;
    __syncthreads();
    if (tid == 0) {
        float mx = red[0];
        #pragma unroll
        for (int i = 1; i < 8; i++) mx = fmaxf(mx, red[i]);
        sh_mx = mx;
    }
    __syncthreads();
    float ev = expf(sc - sh_mx);
    float sv = ev;
    #pragma unroll
    for (int o = 16; o; o >>= 1) sv += __shfl_xor_sync(0xffffffffu, sv, o);
    if (lane == 0) red[warp] = sv;
    __syncthreads();
    if (tid == 0) {
        float s = 0.f;
        #pragma unroll
        for (int i = 0; i < 8; i++) s += red[i];
        sh_sum = s;
    }
    __syncthreads();
    alpha[tid] = ev / sh_sum;
    __syncthreads();

    const float* abase = &g_a[0][m][0];
    for (int j = tid; j < NS; j += 256) {
        float accv = 0.f;
        #pragma unroll 8
        for (int t2 = 0; t2 < TX; t2++)
            accv += alpha[t2] * abase[(size_t)t2 * MB * NS + j];
        g_ctx[m][j] = accv;
    }
}

// ---------------- decoder LSTM cell ----------------
__global__ void dec_cell_kernel(const float* __restrict__ Wih, const float* __restrict__ Whh,
                                const float* __restrict__ bc, int pin)
{
    int u0 = blockIdx.x * 16;
    int m0 = blockIdx.y * 64;
    int tid = threadIdx.x;
    int ul = tid & 15, mg = tid >> 4;
    int u = u0 + ul;

    __shared__ float As[64][33];
    __shared__ float Ws[64][33];

    float acc[4][4];
    #pragma unroll
    for (int mi = 0; mi < 4; mi++)
        #pragma unroll
        for (int g = 0; g < 4; g++)
            acc[mi][g] = bc[g * NS + u];

    for (int ph = 0; ph < 2; ph++) {
        const float* Arow = ph ? &g_sbuf[pin][0][0] : &g_ctx[0][0];
        const float* W = ph ? Whh : Wih;
        for (int k0 = 0; k0 < NS; k0 += 32) {
            #pragma unroll
            for (int i = 0; i < 8; i++) {
                int lin = tid + 256 * i;
                int row = lin >> 5, k = lin & 31;
                As[row][k] = Arow[(size_t)(m0 + row) * NS + k0 + k];
            }
            #pragma unroll
            for (int i = 0; i < 8; i++) {
                int lin = tid + 256 * i;
                int gr = lin >> 5, k = lin & 31;
                int g = gr >> 4, uu = gr & 15;
                Ws[gr][k] = W[(size_t)(g * NS + u0 + uu) * NS + k0 + k];
            }
            __syncthreads();
            #pragma unroll
            for (int kk = 0; kk < 32; kk++) {
                float a_[4], w_[4];
                #pragma unroll
                for (int mi = 0; mi < 4; mi++) a_[mi] = As[mg * 4 + mi][kk];
                #pragma unroll
                for (int g = 0; g < 4; g++) w_[g] = Ws[g * 16 + ul][kk];
                #pragma unroll
                for (int mi = 0; mi < 4; mi++)
                    #pragma unroll
                    for (int g = 0; g < 4; g++)
                        acc[mi][g] += a_[mi] * w_[g];
            }
            __syncthreads();
        }
    }

    #pragma unroll
    for (int mi = 0; mi < 4; mi++) {
        int m = m0 + mg * 4 + mi;
        float ig = sigf(acc[mi][0]);
        float fg = sigf(acc[mi][1]);
        float gg = tanhf(acc[mi][2]);
        float og = sigf(acc[mi][3]);
        float co = g_cdec[m][u];
        float cn = fg * co + ig * gg;
        g_cdec[m][u] = cn;
        g_sbuf[1 - pin][m][u] = og * tanhf(cn);
    }
}

// ---------------- output projection ----------------
__global__ void fc_kernel(const float* __restrict__ Wfc, const float* __restrict__ bfc,
                          float* __restrict__ outp, int ps, int ty)
{
    int col0 = blockIdx.x * 64;
    int m0 = blockIdx.y * 64;
    int tid = threadIdx.x;
    int ry = tid >> 4, rx = tid & 15;
    __shared__ float As[16][64];
    __shared__ float Bs[16][64];
    float acc[4][4] = {};
    int lr = tid >> 2;
    int lk = (tid & 3) * 4;
    const float* S = &g_sbuf[ps][0][0];
    for (int k0 = 0; k0 < NS; k0 += 16) {
        float4 av = *(const float4*)(S + (size_t)(m0 + lr) * NS + k0 + lk);
        float4 bv = *(const float4*)(Wfc + (size_t)(col0 + lr) * NS + k0 + lk);
        As[lk + 0][lr] = av.x; As[lk + 1][lr] = av.y; As[lk + 2][lr] = av.z; As[lk + 3][lr] = av.w;
        Bs[lk + 0][lr] = bv.x; Bs[lk + 1][lr] = bv.y; Bs[lk + 2][lr] = bv.z; Bs[lk + 3][lr] = bv.w;
        __syncthreads();
        #pragma unroll
        for (int kk = 0; kk < 16; kk++) {
            float a_[4], b_[4];
            #pragma unroll
            for (int i = 0; i < 4; i++) a_[i] = As[kk][ry + 16 * i];
            #pragma unroll
            for (int j = 0; j < 4; j++) b_[j] = Bs[kk][rx + 16 * j];
            #pragma unroll
            for (int i = 0; i < 4; i++)
                #pragma unroll
                for (int j = 0; j < 4; j++)
                    acc[i][j] += a_[i] * b_[j];
        }
        __syncthreads();
    }
    #pragma unroll
    for (int i = 0; i < 4; i++) {
        int m = m0 + ry + 16 * i;
        #pragma unroll
        for (int j = 0; j < 4; j++) {
            int c = col0 + rx + 16 * j;
            outp[((size_t)m * TYD + ty) * VOC + c] = acc[i][j] + bfc[c];
        }
    }
}

// ---------------- launch ----------------
extern "C" void kernel_launch(void* const* d_in, const int* in_sizes, int n_in,
                              void* d_out, int out_size)
{
    const float* X     = (const float*)d_in[0];
    const float* Wih_f = (const float*)d_in[1];
    const float* Whh_f = (const float*)d_in[2];
    const float* b_f   = (const float*)d_in[3];
    const float* Wih_b = (const float*)d_in[4];
    const float* Whh_b = (const float*)d_in[5];
    const float* b_b   = (const float*)d_in[6];
    const float* W1    = (const float*)d_in[7];
    const float* b1    = (const float*)d_in[8];
    const float* W2    = (const float*)d_in[9];
    const float* b2    = (const float*)d_in[10];
    const float* Wc_ih = (const float*)d_in[11];
    const float* Wc_hh = (const float*)d_in[12];
    const float* bc    = (const float*)d_in[13];
    const float* Wfc   = (const float*)d_in[14];
    const float* bfc   = (const float*)d_in[15];
    float* outp = (float*)d_out;

    static int smem_set = 0;
    if (!smem_set) {
        cudaFuncSetAttribute(lstm_all_kernel,
                             cudaFuncAttributeMaxDynamicSharedMemorySize, 196608);
        smem_set = 1;
    }

    zero_bar_kernel<<<1, 32>>>();

    // encoder input projection (both directions)
    xproj_kernel<<<dim3(16, 1024, 2), 256>>>(X, Wih_f, b_f, Wih_b, b_b);

    // persistent recurrence: all 256 steps, both dirs, one kernel
    lstm_all_kernel<<<dim3(16, 4, 2), 128, 196608>>>(Whh_f, Whh_b);

    // hoisted attention energies + decoder state init
    ea_kernel<<<256, 256>>>(W1);
    init_dec_kernel<<<512, 256>>>();

    int pin = 0;
    for (int ty = 0; ty < TYD; ty++) {
        attention_kernel<<<MB, 256>>>(W1, b1, W2, b2, pin);
        dec_cell_kernel<<<dim3(32, 4), 256>>>(Wc_ih, Wc_hh, bc, pin);
        fc_kernel<<<dim3(16, 4), 256>>>(Wfc, bfc, outp, 1 - pin, ty);
        pin = 1 - pin;
    }
}